// round 2
// baseline (speedup 1.0000x reference)
#include <cuda_runtime.h>

// RandomShiftsAug == integer pixel shift with edge clamp (bilinear weights are
// exactly 0 given the reference's linspace/scale arithmetic):
//   out[n,c,j,i] = x[n,c, clamp(j+sy-PAD,0,H-1), clamp(i+sx-PAD,0,W-1)]
//
// R2: replace 4 scalar gathers with 1-2 aligned LDG.128 + warp-uniform swizzle
// (sx is uniform per image, so r = (i0+sx)&3 is warp-uniform). Interior blocks
// (w4 in [1,19]) never clamp because |sx| <= PAD. Edge blocks (w4 in {0,20})
// are handled by a contiguous tail region of threads -> no intra-warp
// divergence in the hot path.

#define C_   4
#define H_   84
#define W_   84
#define PAD_ 4
#define W4_  21      // float4 blocks per row (rows are 336B, 16B-aligned)
#define IW4_ 19      // interior blocks per row

__global__ void __launch_bounds__(256) shift_copy_kernel(
    const float* __restrict__ x,
    const int*   __restrict__ shift,
    float*       __restrict__ out,
    int interior_total,   // n*C*H*19
    int edge_half,        // n*C*H      (count of w4==0 blocks)
    int total)            // interior_total + 2*edge_half
{
    int idx = blockIdx.x * blockDim.x + threadIdx.x;
    if (idx >= total) return;

    if (idx < interior_total) {
        // ---- interior: aligned vector loads + uniform swizzle ----
        int w4 = idx % IW4_ + 1;
        int t  = idx / IW4_;
        int j  = t % H_;
        int nc = t / H_;          // n*C + c
        int n  = nc >> 2;

        int sx = __ldg(shift + 2 * n + 0) - PAD_;
        int sy = __ldg(shift + 2 * n + 1) - PAD_;

        int ys = min(max(j + sy, 0), H_ - 1);
        const float4* row4 = reinterpret_cast<const float4*>(x + (nc * H_ + ys) * W_);

        int s = w4 * 4 + sx;      // in [0, 80] for interior blocks
        int q = s >> 2;
        int r = s & 3;            // warp-uniform (sx uniform per image)

        float4 A = __ldg(row4 + q);
        float4 v;
        if (r == 0) {
            v = A;
        } else {
            float4 B = __ldg(row4 + q + 1);
            if (r == 1)      v = make_float4(A.y, A.z, A.w, B.x);
            else if (r == 2) v = make_float4(A.z, A.w, B.x, B.y);
            else             v = make_float4(A.w, B.x, B.y, B.z);
        }
        reinterpret_cast<float4*>(out)[(nc * H_ + j) * W4_ + w4] = v;
    } else {
        // ---- edges: scalar clamped gather (contiguous thread range) ----
        int e  = idx - interior_total;
        int w4 = 0;
        if (e >= edge_half) { w4 = W4_ - 1; e -= edge_half; }
        int j  = e % H_;
        int nc = e / H_;
        int n  = nc >> 2;

        int sx = __ldg(shift + 2 * n + 0) - PAD_;
        int sy = __ldg(shift + 2 * n + 1) - PAD_;

        int ys = min(max(j + sy, 0), H_ - 1);
        const float* row = x + (nc * H_ + ys) * W_;

        int i0 = w4 * 4;
        float4 v;
        v.x = __ldg(row + min(max(i0 + 0 + sx, 0), W_ - 1));
        v.y = __ldg(row + min(max(i0 + 1 + sx, 0), W_ - 1));
        v.z = __ldg(row + min(max(i0 + 2 + sx, 0), W_ - 1));
        v.w = __ldg(row + min(max(i0 + 3 + sx, 0), W_ - 1));
        reinterpret_cast<float4*>(out)[(nc * H_ + j) * W4_ + w4] = v;
    }
}

extern "C" void kernel_launch(void* const* d_in, const int* in_sizes, int n_in,
                              void* d_out, int out_size)
{
    const float* x     = (const float*)d_in[0];
    const int*   shift = (const int*)d_in[1];
    float*       out   = (float*)d_out;

    int n = in_sizes[0] / (C_ * H_ * W_);
    int rows           = n * C_ * H_;
    int interior_total = rows * IW4_;
    int edge_half      = rows;
    int total          = interior_total + 2 * edge_half;

    int threads = 256;
    int blocks  = (total + threads - 1) / threads;
    shift_copy_kernel<<<blocks, threads>>>(x, shift, out,
                                           interior_total, edge_half, total);
}

// round 3
// speedup vs baseline: 1.6469x; 1.6469x over previous
#include <cuda_runtime.h>

// RandomShiftsAug == integer pixel shift with edge clamp (the reference's
// bilinear weights are exactly zero given its linspace/scale arithmetic):
//   out[n,c,j,i] = x[n,c, clamp(j+sy-PAD,0,H-1), clamp(i+sx-PAD,0,W-1)]
// shift: (N,1,1,2) int32; [...,0]=sx, [...,1]=sy; same for all 4 channels of n.
//
// R3: one block per (n,c) plane. Stage the plane in SMEM via aligned coalesced
// float4 copy (exact compulsory DRAM reads), pad row edges in SMEM, then build
// each output float4 from two SMEM LDS.128 + warp-uniform swizzle and write a
// fully contiguous coalesced float4 store stream (exact compulsory writes).

#define C_   4
#define H_   84
#define W_   84
#define PAD_ 4
#define W4_  21          // float4 blocks per 84-float row
#define RP_  96          // padded SMEM row: [0..3]=left pad, [4..87]=row, [88..91]=right pad
#define NBLK (H_ * W4_)  // 1764 float4 blocks per plane

__global__ void __launch_bounds__(256) shift_smem_kernel(
    const float* __restrict__ x,
    const int*   __restrict__ shift,
    float*       __restrict__ out)
{
    __shared__ float s[H_ * RP_];   // 84*96*4 = 32256 B

    const int nc  = blockIdx.x;     // n*4 + c
    const int n   = nc >> 2;
    const int tid = threadIdx.x;

    const int sx = __ldg(shift + 2 * n + 0) - PAD_;   // in [-4, 4]
    const int sy = __ldg(shift + 2 * n + 1) - PAD_;

    // ---- phase 1: coalesced aligned stage GMEM -> SMEM ----
    const float4* in4 = reinterpret_cast<const float4*>(x) + nc * NBLK;
    #pragma unroll
    for (int it = 0; it < 7; ++it) {
        int m = tid + it * 256;
        if (m < NBLK) {
            int row = m / W4_;
            int w4  = m - row * W4_;
            float4 v = __ldg(in4 + m);
            *reinterpret_cast<float4*>(&s[row * RP_ + 4 + w4 * 4]) = v;
        }
    }
    __syncthreads();

    // ---- phase 2: fill edge pads (edge-clamp clones) ----
    if (tid < H_) {
        int base = tid * RP_;
        float l = s[base + 4];
        float r = s[base + 87];
        s[base + 0] = l; s[base + 1] = l; s[base + 2] = l; s[base + 3] = l;
        s[base + 88] = r; s[base + 89] = r; s[base + 90] = r; s[base + 91] = r;
    }
    __syncthreads();

    // ---- phase 3: swizzle from SMEM, coalesced float4 stores ----
    float4* out4 = reinterpret_cast<float4*>(out) + nc * NBLK;
    #pragma unroll
    for (int it = 0; it < 7; ++it) {
        int m = tid + it * 256;
        if (m < NBLK) {
            int j  = m / W4_;
            int w4 = m - j * W4_;

            int ys = min(max(j + sy, 0), H_ - 1);
            int pp = 4 + w4 * 4 + sx;      // padded start index in [0, 88]
            int q  = pp >> 2;
            int r  = pp & 3;               // == (sx & 3): warp-uniform per image

            const float4* row4 = reinterpret_cast<const float4*>(&s[ys * RP_]);
            float4 A = row4[q];
            float4 v;
            if (r == 0) {
                v = A;
            } else {
                float4 B = row4[q + 1];    // r!=0 implies q+1 <= 22 (right pad covers it)
                if (r == 1)      v = make_float4(A.y, A.z, A.w, B.x);
                else if (r == 2) v = make_float4(A.z, A.w, B.x, B.y);
                else             v = make_float4(A.w, B.x, B.y, B.z);
            }
            out4[m] = v;
        }
    }
}

extern "C" void kernel_launch(void* const* d_in, const int* in_sizes, int n_in,
                              void* d_out, int out_size)
{
    const float* x     = (const float*)d_in[0];
    const int*   shift = (const int*)d_in[1];
    float*       out   = (float*)d_out;

    int n = in_sizes[0] / (C_ * H_ * W_);
    shift_smem_kernel<<<n * C_, 256>>>(x, shift, out);
}